// round 15
// baseline (speedup 1.0000x reference)
#include <cuda_runtime.h>
#include <cuda_fp16.h>

// Problem constants
#define L_   4096
#define C_   512
#define H_   8
#define D_   64
#define NB   4
#define NHT  32            // NB * H_
#define KS_  9
#define ASPL 8             // attn L-splits
#define INV_PI 0.31830988618379067154f

// Scratch (static device globals — allocation-free per harness rules)
__device__ __half g_qh[(size_t)NB * H_ * L_ * D_];
__device__ __half g_kh[(size_t)NB * H_ * L_ * D_];
__device__ __half g_vh[(size_t)NB * H_ * L_ * D_];
__device__ float  g_part[(size_t)ASPL * NHT * D_ * D_];
__device__ float  g_attn[(size_t)NHT * D_ * D_];
__device__ __half g_xh[(size_t)NB * L_ * C_];        // x in fp16
__device__ __half g_midh[(size_t)NB * L_ * C_];      // mid in fp16
__device__ __half g_wqh_t[(size_t)(3 * C_) * C_];    // w_qkv^T [N][K] fp16
__device__ __half g_wph_t[(size_t)C_ * C_];          // w_proj^T [N][K] fp16

// ---------------------------------------------------------------------------
// Helpers
// ---------------------------------------------------------------------------
__device__ __forceinline__ float f2tf(float x) {
    unsigned y;
    asm("cvt.rna.tf32.f32 %0, %1;" : "=r"(y) : "f"(x));
    return __uint_as_float(y);
}
__device__ __forceinline__ unsigned f2tfb(float x) {
    unsigned y;
    asm("cvt.rna.tf32.f32 %0, %1;" : "=r"(y) : "f"(x));
    return y;
}
__device__ __forceinline__ void mma_tf32(float* c, const unsigned* a, const unsigned* b) {
    asm volatile(
        "mma.sync.aligned.m16n8k8.row.col.f32.tf32.tf32.f32 "
        "{%0,%1,%2,%3}, {%4,%5,%6,%7}, {%8,%9}, {%0,%1,%2,%3};\n"
        : "+f"(c[0]), "+f"(c[1]), "+f"(c[2]), "+f"(c[3])
        : "r"(a[0]), "r"(a[1]), "r"(a[2]), "r"(a[3]),
          "r"(b[0]), "r"(b[1]));
}
__device__ __forceinline__ void mma_f16(float* c, const unsigned* a, const unsigned* b) {
    asm volatile(
        "mma.sync.aligned.m16n8k16.row.col.f32.f16.f16.f32 "
        "{%0,%1,%2,%3}, {%4,%5,%6,%7}, {%8,%9}, {%0,%1,%2,%3};\n"
        : "+f"(c[0]), "+f"(c[1]), "+f"(c[2]), "+f"(c[3])
        : "r"(a[0]), "r"(a[1]), "r"(a[2]), "r"(a[3]),
          "r"(b[0]), "r"(b[1]));
}
__device__ __forceinline__ void cp16(unsigned dst, const void* src) {
    asm volatile("cp.async.cg.shared.global [%0], [%1], 16;\n"
                 :: "r"(dst), "l"(src));
}
__device__ __forceinline__ float2 h2f2(unsigned w) {
    __half2 h = *(__half2*)&w;
    return __half22float2(h);
}

// ---------------------------------------------------------------------------
// Convert kernels (also shift ncu's captured 4th slot onto the QKV GEMM)
// ---------------------------------------------------------------------------
__global__ __launch_bounds__(256) void cvt_x_kernel(const float* __restrict__ x)
{
    int i = blockIdx.x * 256 + threadIdx.x;          // over float4s (2M)
    float4 t = ((const float4*)x)[i];
    ((__half2*)g_xh)[2 * i] = __floats2half2_rn(t.x, t.y);
    ((__half2*)g_xh)[2 * i + 1] = __floats2half2_rn(t.z, t.w);
}

template <int SEL>   // 0: w_qkv -> g_wqh_t (N=1536), 1: w_proj -> g_wph_t (N=512)
__global__ __launch_bounds__(256) void cvt_wT_kernel(const float* __restrict__ w)
{
    const int N = (SEL == 0) ? (3 * C_) : C_;
    __half* dst = (SEL == 0) ? g_wqh_t : g_wph_t;
    int idx = blockIdx.x * 256 + threadIdx.x;        // over N*K
    int n = idx >> 9;                                 // K = 512
    int k = idx & 511;
    dst[idx] = __float2half(w[(size_t)k * N + n]);
}

// ---------------------------------------------------------------------------
// FP16 GEMM v7: 256 threads / 8 warps (64x32 warp tiles) + BK=32 cp.async
// 3-stage ring. Rationale: R13 measured 42 cyc/mma vs ~16 floor with only
// 2 warps/SMSP (latency-bound); halving acc regs doubles warps/SMSP while
// the async ring keeps staging off the critical path (unlike R10's LDG loop).
//   Row pitch PW32=20 words per 32-half row (20g mod 32 spans all banks).
// Per-element k-accumulation order unchanged -> rel_err reproduces 5.684e-4.
// MODE 0: scatter fp16 into g_qh/g_kh/g_vh [N,H,L,D]; MODE 1: fp32 row-major.
// ---------------------------------------------------------------------------
#define PW32 20
#define STG32 (128 * PW32)          // words per stage per operand (10240 B)
#define GEMM_DSMEM (6 * STG32 * 4)  // 61440 B

template <int MODE>
__global__ __launch_bounds__(256) void h16_gemm_cp(
    const float* __restrict__ bias, float* __restrict__ Cout,
    int M, int N, int K)
{
    extern __shared__ unsigned dynsm[];
    unsigned* Asm = dynsm;                    // 3 stages
    unsigned* Bsm = dynsm + 3 * STG32;        // 3 stages

    const __half* Ah = (MODE == 0) ? g_xh : g_midh;
    const __half* Bt = (MODE == 0) ? g_wqh_t : g_wph_t;

    const int tid = threadIdx.x;
    const int lane = tid & 31;
    const int warp = tid >> 5;          // 0..7
    const int warp_m = warp >> 2;       // 0..1
    const int warp_n = warp & 3;        // 0..3
    const int g = lane >> 2;            // 0..7
    const int tig = lane & 3;           // 0..3

    const int bn = blockIdx.x;
    const int bm = blockIdx.y;

    const __half* Ablk = Ah + (size_t)bm * 128 * K;
    const __half* Bblk = Bt + (size_t)bn * 128 * K;

    const unsigned aBase = (unsigned)__cvta_generic_to_shared(Asm);
    const unsigned bBase = (unsigned)__cvta_generic_to_shared(Bsm);

    float acc[4][4][4];
#pragma unroll
    for (int mt = 0; mt < 4; mt++)
#pragma unroll
        for (int nt = 0; nt < 4; nt++)
#pragma unroll
            for (int i = 0; i < 4; i++) acc[mt][nt][i] = 0.f;

    const int NIT = K >> 5;             // 16
    const unsigned stgBytes = STG32 * 4;

    // prologue: chunks 0,1 (256 thr x 2 cp16 per operand = 512 x 16B)
#pragma unroll
    for (int ch = 0; ch < 2; ch++) {
        unsigned so = ch * stgBytes;
        int kc = ch * 32;
#pragma unroll
        for (int p = 0; p < 2; p++) {
            int idx = tid + p * 256;
            int row = idx >> 2, qt = idx & 3;
            unsigned doff = so + (unsigned)(row * PW32 + qt * 4) * 4;
            cp16(aBase + doff, Ablk + (size_t)row * K + kc + qt * 8);
            cp16(bBase + doff, Bblk + (size_t)row * K + kc + qt * 8);
        }
        asm volatile("cp.async.commit_group;\n");
    }

    for (int it = 0; it < NIT; it++) {
        asm volatile("cp.async.wait_group 1;\n" ::: "memory");
        __syncthreads();
        if (it + 2 < NIT) {
            int ch = it + 2;
            unsigned so = (ch % 3) * stgBytes;
            int kc = ch * 32;
#pragma unroll
            for (int p = 0; p < 2; p++) {
                int idx = tid + p * 256;
                int row = idx >> 2, qt = idx & 3;
                unsigned doff = so + (unsigned)(row * PW32 + qt * 4) * 4;
                cp16(aBase + doff, Ablk + (size_t)row * K + kc + qt * 8);
                cp16(bBase + doff, Bblk + (size_t)row * K + kc + qt * 8);
            }
        }
        asm volatile("cp.async.commit_group;\n");

        const unsigned* Ab = Asm + (it % 3) * STG32;
        const unsigned* Bb = Bsm + (it % 3) * STG32;
#pragma unroll
        for (int s = 0; s < 2; s++) {       // two k16 substeps, k ascending
            const int kb = s * 8;
            unsigned af[4][4], bf[4][2];
#pragma unroll
            for (int mt = 0; mt < 4; mt++) {
                int m0 = warp_m * 64 + mt * 16 + g;
                af[mt][0] = Ab[m0 * PW32 + kb + tig];
                af[mt][1] = Ab[(m0 + 8) * PW32 + kb + tig];
                af[mt][2] = Ab[m0 * PW32 + kb + tig + 4];
                af[mt][3] = Ab[(m0 + 8) * PW32 + kb + tig + 4];
            }
#pragma unroll
            for (int nt = 0; nt < 4; nt++) {
                int n0 = warp_n * 32 + nt * 8 + g;
                bf[nt][0] = Bb[n0 * PW32 + kb + tig];
                bf[nt][1] = Bb[n0 * PW32 + kb + tig + 4];
            }
#pragma unroll
            for (int mt = 0; mt < 4; mt++)
#pragma unroll
                for (int nt = 0; nt < 4; nt++)
                    mma_f16(acc[mt][nt], af[mt], bf[nt]);
        }
    }

    // epilogue
#pragma unroll
    for (int mt = 0; mt < 4; mt++) {
        int r0 = bm * 128 + warp_m * 64 + mt * 16 + g;
#pragma unroll
        for (int nt = 0; nt < 4; nt++) {
            int col = bn * 128 + warp_n * 32 + nt * 8 + 2 * tig;
            float b0 = bias[col];
            float b1 = bias[col + 1];
            float2 v01 = make_float2(acc[mt][nt][0] + b0, acc[mt][nt][1] + b1);
            float2 v23 = make_float2(acc[mt][nt][2] + b0, acc[mt][nt][3] + b1);
            if (MODE == 0) {
                int s = col >> 9;
                int h = (col >> 6) & 7;
                int d = col & 63;                  // even
                __half* dst = (s == 0) ? g_qh : ((s == 1) ? g_kh : g_vh);
                int n0r = r0 >> 12, l0r = r0 & (L_ - 1);
                size_t base = (((size_t)n0r * H_ + h) * L_) * D_ + d;
                *(__half2*)(dst + base + (size_t)l0r * D_) = __floats2half2_rn(v01.x, v01.y);
                *(__half2*)(dst + base + (size_t)(l0r + 8) * D_) = __floats2half2_rn(v23.x, v23.y);
            } else {
                *(float2*)(Cout + (size_t)r0 * N + col) = v01;
                *(float2*)(Cout + (size_t)(r0 + 8) * N + col) = v23;
            }
        }
    }
}

// ---------------------------------------------------------------------------
// attn partial (R13 measured version, byte-identical — unchanged)
// ---------------------------------------------------------------------------
__global__ __launch_bounds__(256) void attn_mma_kernel()
{
    __shared__ alignas(16) float ks[64][72];
    __shared__ alignas(16) float vs[64][72];
    __shared__ float invn[64];

    const int tid = threadIdx.x;
    const int split = blockIdx.x;
    const int nh = blockIdx.y;
    const int lane = tid & 31;
    const int warp = tid >> 5;
    const int warp_m = warp >> 1;
    const int warp_n = warp & 1;
    const int g = lane >> 2;
    const int tig = lane & 3;

    const __half* kp = g_kh + (size_t)nh * L_ * D_;
    const __half* vp = g_vh + (size_t)nh * L_ * D_;

    float acc[4][4];
#pragma unroll
    for (int nt = 0; nt < 4; nt++)
#pragma unroll
        for (int i = 0; i < 4; i++) acc[nt][i] = 0.f;

    const int rr = tid >> 2;
    const int cc = tid & 3;

    for (int t = 0; t < 8; t++) {
        int l0 = split * (L_ / ASPL) + t * 64;
#pragma unroll
        for (int p = 0; p < 4; p++) {
            int fi = tid + p * 256;
            int r = fi >> 4, c = (fi & 15) * 4;
            uint2 kw = *(const uint2*)(kp + (size_t)(l0 + r) * D_ + c);
            uint2 vw = *(const uint2*)(vp + (size_t)(l0 + r) * D_ + c);
            float2 k01 = h2f2(kw.x), k23 = h2f2(kw.y);
            float2 v01 = h2f2(vw.x), v23 = h2f2(vw.y);
            ks[r][c + 0] = k01.x; ks[r][c + 1] = k01.y;
            ks[r][c + 2] = k23.x; ks[r][c + 3] = k23.y;
            vs[r][c + 0] = v01.x; vs[r][c + 1] = v01.y;
            vs[r][c + 2] = v23.x; vs[r][c + 3] = v23.y;
        }
        __syncthreads();
        {
            float s = 0.f;
#pragma unroll
            for (int j = 0; j < 16; j++) {
                float x = ks[rr][cc * 16 + j];
                s = fmaf(x, x, s);
            }
            s += __shfl_xor_sync(0xffffffffu, s, 1);
            s += __shfl_xor_sync(0xffffffffu, s, 2);
            if (cc == 0) invn[rr] = 1.0f / sqrtf(s);
        }
        __syncthreads();

        const int d0 = warp_m * 16;
#pragma unroll
        for (int kstep = 0; kstep < 8; kstep++) {
            int k0 = kstep * 8;
            float s0 = invn[k0 + tig];
            float s1 = invn[k0 + tig + 4];
            unsigned a[4];
            a[0] = f2tfb(ks[k0 + tig][d0 + g] * s0);
            a[1] = f2tfb(ks[k0 + tig][d0 + g + 8] * s0);
            a[2] = f2tfb(ks[k0 + tig + 4][d0 + g] * s1);
            a[3] = f2tfb(ks[k0 + tig + 4][d0 + g + 8] * s1);
#pragma unroll
            for (int nt = 0; nt < 4; nt++) {
                int n0 = warp_n * 32 + nt * 8;
                unsigned b[2];
                b[0] = __float_as_uint(vs[k0 + tig][n0 + g]);
                b[1] = __float_as_uint(vs[k0 + tig + 4][n0 + g]);
                mma_tf32(acc[nt], a, b);
            }
        }
        __syncthreads();
    }

    float* out = g_part + ((size_t)split * NHT + nh) * (D_ * D_);
    const int dA = warp_m * 16 + g;
    const int dB = dA + 8;
#pragma unroll
    for (int nt = 0; nt < 4; nt++) {
        int e = warp_n * 32 + nt * 8 + 2 * tig;
        *(float2*)&out[dA * 64 + e] = make_float2(acc[nt][0], acc[nt][1]);
        *(float2*)&out[dB * 64 + e] = make_float2(acc[nt][2], acc[nt][3]);
    }
}

__global__ __launch_bounds__(256) void attn_reduce_kernel()
{
    int idx = blockIdx.x * 256 + threadIdx.x;
    int nh = idx >> 12;
    int rem = idx & 4095;
    float s = 0.f;
#pragma unroll
    for (int sp = 0; sp < ASPL; sp++)
        s += g_part[((size_t)sp * NHT + nh) * 4096 + rem];
    g_attn[idx] = INV_PI * s;
}

// ---------------------------------------------------------------------------
// out kernel (R13 measured version, byte-identical — unchanged)
// ---------------------------------------------------------------------------
#define PQ 76
#define PAT 72
#define OQ(r, c)  sm_q[(r) * PQ + (c)]
#define OA(r, c)  sm_a[(r) * PAT + (c)]
#define OV(r, c)  sm_v[(r) * 68 + (c)]
#define OUT_SMEM_FLOATS (64 * PQ + 64 * PAT + 72 * 68 + 64 + 128 + 16)

__global__ __launch_bounds__(256) void out_kernel(const float* __restrict__ wdc)
{
    extern __shared__ float sm[];
    float* sm_q = sm;
    float* sm_a = sm_q + 64 * PQ;
    float* sm_v = sm_a + 64 * PAT;
    float* invq = sm_v + 72 * 68;
    float* ssq_s = invq + 64;
    float* wc = ssq_s + 128;

    const int tid = threadIdx.x;
    const int nh = blockIdx.y;
    const int n = nh >> 3, h = nh & 7;
    const int l0 = blockIdx.x * 64;

    const __half* qp = g_qh + (size_t)nh * L_ * D_;
    const __half* vp = g_vh + (size_t)nh * L_ * D_;
    const float* ap = g_attn + (size_t)nh * 4096;

#pragma unroll
    for (int p = 0; p < 4; p++) {
        int fi = tid + p * 256;
        int r = fi >> 4, c = (fi & 15) * 4;
        float4 a = *(const float4*)(ap + r * 64 + c);
        OA(r, c + 0) = f2tf(a.x); OA(r, c + 1) = f2tf(a.y);
        OA(r, c + 2) = f2tf(a.z); OA(r, c + 3) = f2tf(a.w);
        uint2 qw = *(const uint2*)(qp + (size_t)(l0 + r) * D_ + c);
        float2 q01 = h2f2(qw.x), q23 = h2f2(qw.y);
        OQ(r, c + 0) = q01.x; OQ(r, c + 1) = q01.y;
        OQ(r, c + 2) = q23.x; OQ(r, c + 3) = q23.y;
    }
    for (int fi = tid; fi < 72 * 16; fi += 256) {
        int r = fi >> 4, c = (fi & 15) * 4;
        int gl = l0 - 4 + r;
        float4 val = make_float4(0.f, 0.f, 0.f, 0.f);
        if (gl >= 0 && gl < L_) {
            uint2 vw = *(const uint2*)(vp + (size_t)gl * D_ + c);
            float2 v01 = h2f2(vw.x), v23 = h2f2(vw.y);
            val = make_float4(v01.x, v01.y, v23.x, v23.y);
        }
        *(float4*)&OV(r, c) = val;
    }
    if (tid < KS_) wc[tid] = wdc[h * KS_ + tid];
    __syncthreads();

    {
        int rr = tid >> 2, cc = tid & 3;
        float s = 0.f;
#pragma unroll
        for (int j = 0; j < 16; j++) {
            float x = OQ(rr, cc * 16 + j);
            s = fmaf(x, x, s);
        }
        s += __shfl_xor_sync(0xffffffffu, s, 1);
        s += __shfl_xor_sync(0xffffffffu, s, 2);
        if (cc == 0) invq[rr] = 1.0f / sqrtf(s);
    }
    __syncthreads();

    const int lane = tid & 31;
    const int warp = tid >> 5;
    const int warp_m = warp >> 1;
    const int warp_n = warp & 1;
    const int g = lane >> 2;
    const int tig = lane & 3;

    float acc[4][4];
#pragma unroll
    for (int nt = 0; nt < 4; nt++)
#pragma unroll
        for (int i = 0; i < 4; i++) acc[nt][i] = 0.f;

    const int m0 = warp_m * 16;
#pragma unroll
    for (int kstep = 0; kstep < 8; kstep++) {
        int k0 = kstep * 8;
        unsigned a[4];
        a[0] = __float_as_uint(OQ(m0 + g, k0 + tig));
        a[1] = __float_as_uint(OQ(m0 + g + 8, k0 + tig));
        a[2] = __float_as_uint(OQ(m0 + g, k0 + tig + 4));
        a[3] = __float_as_uint(OQ(m0 + g + 8, k0 + tig + 4));
#pragma unroll
        for (int nt = 0; nt < 4; nt++) {
            int n0 = warp_n * 32 + nt * 8;
            unsigned b[2];
            b[0] = __float_as_uint(OA(k0 + tig, n0 + g));
            b[1] = __float_as_uint(OA(k0 + tig + 4, n0 + g));
            mma_tf32(acc[nt], a, b);
        }
    }
    __syncthreads();

    {
        const int rA = warp_m * 16 + g;
        const int rB = rA + 8;
        const float iqA = invq[rA];
        const float iqB = invq[rB];
        float ssqA = 0.f, ssqB = 0.f;
#pragma unroll
        for (int nt = 0; nt < 4; nt++) {
            int c = warp_n * 32 + nt * 8 + 2 * tig;
            float2 vA = *(const float2*)&OV(4 + rA, c);
            float2 vB = *(const float2*)&OV(4 + rB, c);
            float pA0 = fmaf(0.5f, vA.x, acc[nt][0] * iqA);
            float pA1 = fmaf(0.5f, vA.y, acc[nt][1] * iqA);
            float pB0 = fmaf(0.5f, vB.x, acc[nt][2] * iqB);
            float pB1 = fmaf(0.5f, vB.y, acc[nt][3] * iqB);
            ssqA = fmaf(pA0, pA0, ssqA); ssqA = fmaf(pA1, pA1, ssqA);
            ssqB = fmaf(pB0, pB0, ssqB); ssqB = fmaf(pB1, pB1, ssqB);
            *(float2*)&OA(rA, c) = make_float2(pA0, pA1);
            *(float2*)&OA(rB, c) = make_float2(pB0, pB1);
        }
        ssqA += __shfl_xor_sync(0xffffffffu, ssqA, 1);
        ssqA += __shfl_xor_sync(0xffffffffu, ssqA, 2);
        ssqB += __shfl_xor_sync(0xffffffffu, ssqB, 1);
        ssqB += __shfl_xor_sync(0xffffffffu, ssqB, 2);
        if (tig == 0) {
            ssq_s[warp_n * 64 + rA] = ssqA;
            ssq_s[warp_n * 64 + rB] = ssqB;
        }
    }
    __syncthreads();

    {
        const int r = tid >> 2;
        const int e0 = (tid & 3) * 16;
        float inv2 = 1.0f / sqrtf(ssq_s[r] + ssq_s[64 + r]);

        float dc[16];
#pragma unroll
        for (int j = 0; j < 16; j++) dc[j] = 0.f;
#pragma unroll
        for (int t = 0; t < KS_; t++) {
            float w = wc[t];
#pragma unroll
            for (int jc = 0; jc < 4; jc++) {
                float4 vv = *(const float4*)&OV(r + t, e0 + jc * 4);
                dc[jc * 4 + 0] = fmaf(w, vv.x, dc[jc * 4 + 0]);
                dc[jc * 4 + 1] = fmaf(w, vv.y, dc[jc * 4 + 1]);
                dc[jc * 4 + 2] = fmaf(w, vv.z, dc[jc * 4 + 2]);
                dc[jc * 4 + 3] = fmaf(w, vv.w, dc[jc * 4 + 3]);
            }
        }

        __half* mp = g_midh + ((size_t)(n * L_ + l0 + r)) * C_ + h * D_ + e0;
#pragma unroll
        for (int jc = 0; jc < 4; jc++) {
            float4 p = *(const float4*)&OA(r, e0 + jc * 4);
            float ox = fmaf(p.x, inv2, dc[jc * 4 + 0]);
            float oy = fmaf(p.y, inv2, dc[jc * 4 + 1]);
            float oz = fmaf(p.z, inv2, dc[jc * 4 + 2]);
            float ow = fmaf(p.w, inv2, dc[jc * 4 + 3]);
            *(__half2*)(mp + jc * 4) = __floats2half2_rn(ox, oy);
            *(__half2*)(mp + jc * 4 + 2) = __floats2half2_rn(oz, ow);
        }
    }
}

// ---------------------------------------------------------------------------
extern "C" void kernel_launch(void* const* d_in, const int* in_sizes, int n_in,
                              void* d_out, int out_size)
{
    const float* x       = (const float*)d_in[0];   // [4,4096,512]
    const float* w_qkv   = (const float*)d_in[1];   // [512,1536]
    const float* b_qkv   = (const float*)d_in[2];   // [1536]
    const float* w_dconv = (const float*)d_in[3];   // [8,1,9,1]
    const float* w_proj  = (const float*)d_in[4];   // [512,512]
    const float* b_proj  = (const float*)d_in[5];   // [512]
    float* out = (float*)d_out;                      // [4,4096,512]

    const int M = NB * L_;       // 16384
    const int out_smem = OUT_SMEM_FLOATS * (int)sizeof(float);  // ~58 KB

    static bool attr_done = false;
    if (!attr_done) {
        cudaFuncSetAttribute(out_kernel,
                             cudaFuncAttributeMaxDynamicSharedMemorySize, out_smem);
        cudaFuncSetAttribute(h16_gemm_cp<0>,
                             cudaFuncAttributeMaxDynamicSharedMemorySize, GEMM_DSMEM);
        cudaFuncSetAttribute(h16_gemm_cp<1>,
                             cudaFuncAttributeMaxDynamicSharedMemorySize, GEMM_DSMEM);
        attr_done = true;
    }

    // 0. converts (also shift ncu's captured slot onto the QKV GEMM)
    cvt_x_kernel<<<(NB * L_ * C_ / 4) / 256, 256>>>(x);
    cvt_wT_kernel<0><<<(3 * C_ * C_) / 256, 256>>>(w_qkv);
    cvt_wT_kernel<1><<<(C_ * C_) / 256, 256>>>(w_proj);

    // 1. QKV projection (fp16, 8-warp, cp.async BK=32) -> q/k/v fp16 [N,H,L,D]
    h16_gemm_cp<0><<<dim3((3 * C_) / 128, M / 128), 256, GEMM_DSMEM>>>(
        b_qkv, nullptr, M, 3 * C_, C_);

    // 2. attn partials (tf32 mma, fp16 loads)
    attn_mma_kernel<<<dim3(ASPL, NHT), 256>>>();

    // 3. deterministic reduce (+ INV_PI fold)
    attn_reduce_kernel<<<(NHT * D_ * D_) / 256, 256>>>();

    // 4. fused out stage -> g_midh fp16 [N,L,C]
    out_kernel<<<dim3(L_ / 64, NHT), 256, out_smem>>>(w_dconv);

    // 5. output projection -> d_out (fp32)
    h16_gemm_cp<1><<<dim3(C_ / 128, M / 128), 256, GEMM_DSMEM>>>(
        b_proj, out, M, C_, C_);
}